// round 17
// baseline (speedup 1.0000x reference)
#include <cuda_runtime.h>
#include <cuda_fp16.h>
#include <math.h>
#include <cstdint>

// ---------------- problem constants ----------------
#define NQ   300
#define BSZ  8
#define DIM  256
#define NH   8
#define DH   32
#define DFF  1024
#define STOT 13294
#define NTOK (NQ*BSZ)          // 2400
#define TOKF (NTOK*DIM)        // 614400

// weight plane offsets (elements)
#define W_INPROJ 0L
#define W_OUTSA  196608L
#define W_VALUE  262144L
#define W_OFF    327680L
#define W_AW     458752L
#define W_OUTCA  524288L
#define W_LIN1   589824L
#define W_LIN2   851968L
#define W_TOTAL  1114112L

// ---------------- scratch (static device globals; no allocations) ----------------
__device__ float g_qh   [TOKF];
__device__ float g_kh   [TOKF];
__device__ float g_vh   [TOKF];
__device__ float g_sain [TOKF];
__device__ float g_saout[TOKF];
__device__ float g_tgt2 [TOKF];
__device__ float g_off  [NTOK*768];
__device__ __half g_value[(long)BSZ*STOT*DIM];   // fp16 value cache
__device__ float g_cain [TOKF];
__device__ float g_caout[TOKF];
__device__ float g_tgt3 [TOKF];
__device__ float g_f1   [NTOK*DFF];
__device__ float g_f2   [TOKF];
__device__ __half g_wh[W_TOTAL];   // weight fp16 plane

// ---------------- helpers ----------------
__device__ __forceinline__ uint32_t smem_u32(const void* p) {
    uint32_t a;
    asm("{ .reg .u64 t; cvta.to.shared.u64 t, %1; cvt.u32.u64 %0, t; }" : "=r"(a) : "l"(p));
    return a;
}
__device__ __forceinline__ unsigned pkh(__half a, __half b) {
    __half2 t = __halves2half2(a, b);
    return *reinterpret_cast<unsigned*>(&t);
}
__device__ __forceinline__ void mma_f16(float* d, const uint32_t* a, uint32_t b0, uint32_t b1) {
    asm volatile(
        "mma.sync.aligned.m16n8k16.row.col.f32.f16.f16.f32 "
        "{%0,%1,%2,%3}, {%4,%5,%6,%7}, {%8,%9}, {%0,%1,%2,%3};"
        : "+f"(d[0]), "+f"(d[1]), "+f"(d[2]), "+f"(d[3])
        : "r"(a[0]), "r"(a[1]), "r"(a[2]), "r"(a[3]), "r"(b0), "r"(b1));
}
__device__ __forceinline__ void ldmx4(uint32_t* r, uint32_t addr) {
    asm volatile("ldmatrix.sync.aligned.m8n8.x4.shared.b16 {%0,%1,%2,%3}, [%4];"
                 : "=r"(r[0]), "=r"(r[1]), "=r"(r[2]), "=r"(r[3]) : "r"(addr));
}
__device__ __forceinline__ uint2 cvt_a(float4 v) {
    return make_uint2(pkh(__float2half_rn(v.x), __float2half_rn(v.y)),
                      pkh(__float2half_rn(v.z), __float2half_rn(v.w)));
}
__device__ __forceinline__ float4 lda4(const float* p, long dAdd, bool doAdd) {
    float4 v = *(const float4*)p;
    if (doAdd) {
        float4 y = *(const float4*)(p + dAdd);
        v.x += y.x; v.y += y.y; v.z += y.z; v.w += y.w;
    }
    return v;
}
#define CP16(dst, src) \
    asm volatile("cp.async.cg.shared.global [%0], [%1], 16;" \
                 :: "r"(dst), "l"(src) : "memory")
#define CP_COMMIT() asm volatile("cp.async.commit_group;" ::: "memory")
#define CP_WAIT1()  asm volatile("cp.async.wait_group 1;" ::: "memory")

// ============ fp16 1-term GEMM, K-chunk 64 ============
// C = (A [+ Aadd]) (MxK fp32->fp16) * W(NxK fp16)^T + bias
// CTA 64x128, 256 thr, 8 warps of 32x32.
// A: register convert, 2-stage ping-pong (8KB/stage). B: cp.async 3-stage (16KB/stage).
// addMode: 0 none, 1 always, 2 only bn<512. permRows: A row r -> token (r%NQ)*BSZ + r/NQ.
// EPI: 0 plain, 1 relu, 2 head-permute (C/C2/C3 for n in 0/256/512 bands),
//      3 pad-mask zero -> fp16 out (batched via blockIdx.z).
template<int EPI>
__global__ void __launch_bounds__(256, 2) mma_gemm(
    const float* __restrict__ A, const float* __restrict__ Aadd,
    int addMode, int permRows,
    int lda, long aOff,
    const __half* __restrict__ B, int ldw,
    const float* __restrict__ bias,
    const __half* W2, const float* bias2, int Nsplit,
    float* __restrict__ C, float* __restrict__ C2, float* __restrict__ C3,
    int ldc, long cOff,
    int M, int K,
    const unsigned char* __restrict__ mask, long mOff)
{
    extern __shared__ __align__(128) unsigned char sm[];
    const uint32_t sb = smem_u32(sm);
    const int tid = threadIdx.x;
    const int bm = blockIdx.y * 64;
    const int bn = blockIdx.x * 128;
    A += (long)blockIdx.z * aOff;
    __half* Ch = nullptr;
    if (EPI == 3) Ch = (__half*)C + (long)blockIdx.z * cOff;
    else          C += (long)blockIdx.z * cOff;
    if (Nsplit && bn >= Nsplit) {
        B = W2 - (long)Nsplit * ldw;
        bias = bias2 - Nsplit;
    }
    const bool doAdd = (addMode == 1) || (addMode == 2 && bn < 512);
    const long dAdd = Aadd ? (long)(Aadd - A) : 0;

    const int warp = tid >> 5, lane = tid & 31;
    const int wm = warp & 1, wn = warp >> 1;

    // A: 64 rows x 64 k fp32 = 1024 float4 (4/thr)
    bool agd[4]; const float* aptr[4]; uint32_t asw[4];
#pragma unroll
    for (int j = 0; j < 4; j++) {
        int i = tid + j * 256;
        int row = i >> 4, kq = i & 15;
        int sub = kq >> 3, kq2 = kq & 7;
        int r = bm + row;
        agd[j] = r < M;
        int rr = agd[j] ? r : M - 1;
        int tok = permRows ? ((rr % NQ) * BSZ + (rr / NQ)) : rr;
        aptr[j] = A + (long)tok * lda + kq * 4;
        asw[j] = (uint32_t)(sub * 4096 + row * 64 + (((kq2 >> 1) ^ ((row >> 1) & 3)) << 4) + (kq2 & 1) * 8);
    }
    // B: 128 rows x 64 halves = 1024 x 16B (4/thr), cp.async
    const __half* bp[4]; uint32_t bsw[4];
#pragma unroll
    for (int j = 0; j < 4; j++) {
        int i = tid + j * 256;
        int row = i >> 3, c8 = i & 7;
        int sub = c8 >> 2, c = c8 & 3;
        bp[j] = B + (long)(bn + row) * ldw + sub * 32 + c * 8;
        bsw[j] = (uint32_t)(sub * 8192 + row * 64 + ((c ^ ((row >> 1) & 3)) << 4));
    }

    float acc[2][4][4];
#pragma unroll
    for (int mt = 0; mt < 2; mt++)
#pragma unroll
        for (int nt = 0; nt < 4; nt++)
#pragma unroll
            for (int r = 0; r < 4; r++) acc[mt][nt][r] = 0.f;

    const int nk = K >> 6;   // chunks of 64

#define ISSUE_B(kc, st) do { \
    if ((kc) < nk) { \
        const int kb = (kc) * 64; \
        const uint32_t so = sb + 16384u + (uint32_t)((st) * 16384); \
        CP16(so + bsw[0], bp[0] + kb); \
        CP16(so + bsw[1], bp[1] + kb); \
        CP16(so + bsw[2], bp[2] + kb); \
        CP16(so + bsw[3], bp[3] + kb); \
    } \
    CP_COMMIT(); \
} while (0)

    float4 av[4];

    // prologue
    ISSUE_B(0, 0);
    ISSUE_B(1, 1);
#pragma unroll
    for (int j = 0; j < 4; j++)
        av[j] = agd[j] ? lda4(aptr[j], dAdd, doAdd) : make_float4(0.f,0.f,0.f,0.f);
#pragma unroll
    for (int j = 0; j < 4; j++)
        *(uint2*)(sm + asw[j]) = cvt_a(av[j]);
    if (nk > 1) {
#pragma unroll
        for (int j = 0; j < 4; j++)
            av[j] = agd[j] ? lda4(aptr[j] + 64, dAdd, doAdd) : make_float4(0.f,0.f,0.f,0.f);
    }
    CP_WAIT1();
    __syncthreads();

    for (int kc = 0; kc < nk; kc++) {
        ISSUE_B(kc + 2, (kc + 2) % 3);

        const uint32_t soa = sb + (uint32_t)((kc & 1) * 8192);
        const uint32_t sob = sb + 16384u + (uint32_t)((kc % 3) * 16384);

#pragma unroll
        for (int ks = 0; ks < 4; ks++) {
            const uint32_t suba = soa + (uint32_t)((ks >> 1) * 4096);
            const uint32_t subb = sob + (uint32_t)((ks >> 1) * 8192);
            const int kk = ks & 1;
            uint32_t af[2][4];
#pragma unroll
            for (int mt = 0; mt < 2; mt++) {
                int row = wm * 32 + mt * 16 + (lane & 7) + ((lane >> 3) & 1) * 8;
                int c = 2 * kk + (lane >> 4);
                uint32_t off = (uint32_t)(row * 64 + ((c ^ ((row >> 1) & 3)) << 4));
                ldmx4(af[mt], suba + off);
            }
            uint32_t bf[4][2];
#pragma unroll
            for (int np = 0; np < 2; np++) {
                int row = wn * 32 + np * 16 + (lane & 7) + (lane >> 4) * 8;
                int c = 2 * kk + ((lane >> 3) & 1);
                uint32_t off = (uint32_t)(row * 64 + ((c ^ ((row >> 1) & 3)) << 4));
                uint32_t t[4];
                ldmx4(t, subb + off);
                bf[2*np][0] = t[0]; bf[2*np][1] = t[1];
                bf[2*np+1][0] = t[2]; bf[2*np+1][1] = t[3];
            }
#pragma unroll
            for (int mt = 0; mt < 2; mt++)
#pragma unroll
                for (int nt = 0; nt < 4; nt++)
                    mma_f16(acc[mt][nt], af[mt], bf[nt][0], bf[nt][1]);
        }

        if (kc + 1 < nk) {
            const uint32_t po = (uint32_t)(((kc + 1) & 1) * 8192);
#pragma unroll
            for (int j = 0; j < 4; j++)
                *(uint2*)(sm + po + asw[j]) = cvt_a(av[j]);
            if (kc + 2 < nk) {
                int kb = (kc + 2) * 64;
#pragma unroll
                for (int j = 0; j < 4; j++)
                    av[j] = agd[j] ? lda4(aptr[j] + kb, dAdd, doAdd) : make_float4(0.f,0.f,0.f,0.f);
            }
        }
        CP_WAIT1();
        __syncthreads();
    }
#undef ISSUE_B

    // ---------------- epilogue ----------------
#pragma unroll
    for (int mt = 0; mt < 2; mt++) {
        int r0 = bm + wm * 32 + mt * 16 + (lane >> 2);
#pragma unroll
        for (int nt = 0; nt < 4; nt++) {
            int n0 = bn + wn * 32 + nt * 8 + (lane & 3) * 2;
            float b0 = bias[n0], b1 = bias[n0 + 1];
#pragma unroll
            for (int half = 0; half < 2; half++) {
                int r = r0 + half * 8;
                if (r >= M) continue;
                float v0 = acc[mt][nt][half * 2 + 0] + b0;
                float v1 = acc[mt][nt][half * 2 + 1] + b1;
                if (EPI == 1) { v0 = fmaxf(v0, 0.f); v1 = fmaxf(v1, 0.f); }
                if (EPI == 3) {
                    if (mask[(long)blockIdx.z * mOff + r]) { v0 = 0.f; v1 = 0.f; }
                    *(__half2*)(Ch + (long)r * ldc + n0) =
                        __halves2half2(__float2half_rn(v0), __float2half_rn(v1));
                } else if (EPI == 2) {
                    float* base = C; int nn = n0;
                    if (nn >= 512)      { base = C3; nn -= 512; }
                    else if (nn >= 256) { base = C2; nn -= 256; }
                    int q = r >> 3, bb = r & 7, hh = nn >> 5, d = nn & 31;
                    float* p = base + (((long)(bb * NH + hh)) * NQ + q) * DH + d;
                    p[0] = v0; p[1] = v1;
                } else {
                    float* p = C + (long)r * ldc + n0;
                    p[0] = v0; p[1] = v1;
                }
            }
        }
    }
}

static inline void launch_mma(int epi,
    const float* A, const float* Aadd, int addMode, int permRows,
    int lda, long aOff,
    const __half* B, int ldw, const float* bias,
    const __half* W2, const float* bias2, int Nsplit,
    float* C, float* C2, float* C3, int ldc, long cOff,
    int M, int N, int K, int nz,
    const unsigned char* mask, long mOff)
{
    dim3 grid(N / 128, (M + 63) / 64, nz);
    const int SMEM = 65536;
#define LM(E) do { \
    cudaFuncSetAttribute(mma_gemm<E>, cudaFuncAttributeMaxDynamicSharedMemorySize, SMEM); \
    mma_gemm<E><<<grid,256,SMEM>>>(A,Aadd,addMode,permRows,lda,aOff,B,ldw,bias,W2,bias2,Nsplit, \
                                   C,C2,C3,ldc,cOff,M,K,mask,mOff); } while (0)
    switch (epi) {
        case 0: LM(0); break;
        case 1: LM(1); break;
        case 2: LM(2); break;
        case 3: LM(3); break;
    }
#undef LM
}

// ---------------- weight convert: fp32 -> fp16 plane ----------------
struct WDesc { const float* src[8]; long off[8]; int n4[8]; };
__global__ void cvt_w_kernel(WDesc d, __half* __restrict__ hi)
{
    int w = blockIdx.y;
    int i = blockIdx.x * blockDim.x + threadIdx.x;
    if (i >= d.n4[w]) return;
    float4 v = ((const float4*)d.src[w])[i];
    ((uint2*)(hi + d.off[w]))[i] = make_uint2(
        pkh(__float2half_rn(v.x), __float2half_rn(v.y)),
        pkh(__float2half_rn(v.z), __float2half_rn(v.w)));
}

// ---------------- residual + layernorm ----------------
__global__ void __launch_bounds__(256) ln_kernel(
    const float* __restrict__ A, const float* __restrict__ B, int bBQ,
    const float* __restrict__ g, const float* __restrict__ be,
    float* __restrict__ out)
{
    int t = blockIdx.x * 8 + (threadIdx.x >> 5);
    int lane = threadIdx.x & 31;
    if (t >= NTOK) return;
    const float* ap = A + (long)t * DIM + lane*8;
    long bo;
    if (bBQ) { int q = t >> 3, b = t & 7; bo = (long)(b*NQ + q) * DIM; }
    else     { bo = (long)t * DIM; }
    const float* bp = B + bo + lane*8;

    float4 x0 = *(const float4*)ap,      x1 = *(const float4*)(ap + 4);
    float4 y0 = *(const float4*)bp,      y1 = *(const float4*)(bp + 4);
    float v[8] = {x0.x+y0.x, x0.y+y0.y, x0.z+y0.z, x0.w+y0.w,
                  x1.x+y1.x, x1.y+y1.y, x1.z+y1.z, x1.w+y1.w};
    float s = 0.f;
#pragma unroll
    for (int i = 0; i < 8; i++) s += v[i];
#pragma unroll
    for (int o = 16; o; o >>= 1) s += __shfl_xor_sync(0xffffffffu, s, o);
    float mu = s * (1.f/256.f);
    float s2 = 0.f;
#pragma unroll
    for (int i = 0; i < 8; i++) { float d = v[i] - mu; s2 += d*d; }
#pragma unroll
    for (int o = 16; o; o >>= 1) s2 += __shfl_xor_sync(0xffffffffu, s2, o);
    float inv = rsqrtf(s2 * (1.f/256.f) + 1e-5f);
    int c0 = lane*8;
    float* op = out + (long)t * DIM + c0;
#pragma unroll
    for (int i = 0; i < 8; i++)
        op[i] = (v[i] - mu) * inv * g[c0+i] + be[c0+i];
}

// ---------------- fused self-attention ----------------
__global__ void __launch_bounds__(256) attn_kernel(
    const float* __restrict__ qh, const float* __restrict__ kh,
    const float* __restrict__ vh, float* __restrict__ sa_in)
{
    extern __shared__ float smf[];
    const int bh   = blockIdx.x >> 1;
    const int half = blockIdx.x & 1;
    const int b = bh >> 3, h = bh & 7;
    float* Ks = smf;
    float* Vs = Ks + 300*36;
    float* Qs = Vs + 300*36;
    float* Ps = Qs + 150*32;

    const float scale = 0.17677669529663687f;
    const float* Kg = kh + (long)bh * NQ * DH;
    const float* Vg = vh + (long)bh * NQ * DH;
    const float* Qg = qh + (long)bh * NQ * DH + (long)half * 150 * DH;
    const int tid = threadIdx.x;

    for (int i = tid; i < 2400; i += 256) {
        int r = i >> 3, c4 = (i & 7) << 2;
        float4 kv = *(const float4*)(Kg + r*32 + c4);
        float4 vv = *(const float4*)(Vg + r*32 + c4);
        *(float4*)(Ks + r*36 + c4) = kv;
        *(float4*)(Vs + r*36 + c4) = vv;
    }
    for (int i = tid; i < 1200; i += 256) {
        int r = i >> 3, c4 = (i & 7) << 2;
        float4 qv = *(const float4*)(Qg + r*32 + c4);
        qv.x *= scale; qv.y *= scale; qv.z *= scale; qv.w *= scale;
        *(float4*)(Qs + r*32 + c4) = qv;
    }
    __syncthreads();

    const int warp = tid >> 5, lane = tid & 31;
    float* Pw = Ps + warp * 320;

    for (int q = warp; q < 150; q += 8) {
        float4 qr[8];
#pragma unroll
        for (int d4 = 0; d4 < 8; d4++) qr[d4] = *(const float4*)(Qs + q*32 + d4*4);

        float sc[10];
#pragma unroll
        for (int j = 0; j < 10; j++) {
            int k = j*32 + lane;
            float s = -1e30f;
            if (k < 300) {
                s = 0.f;
#pragma unroll
                for (int d4 = 0; d4 < 8; d4++) {
                    float4 kv = *(const float4*)(Ks + k*36 + d4*4);
                    s = fmaf(qr[d4].x, kv.x, s);
                    s = fmaf(qr[d4].y, kv.y, s);
                    s = fmaf(qr[d4].z, kv.z, s);
                    s = fmaf(qr[d4].w, kv.w, s);
                }
            }
            sc[j] = s;
        }
        float m = sc[0];
#pragma unroll
        for (int j = 1; j < 10; j++) m = fmaxf(m, sc[j]);
#pragma unroll
        for (int o = 16; o; o >>= 1) m = fmaxf(m, __shfl_xor_sync(0xffffffffu, m, o));
        float sum = 0.f;
#pragma unroll
        for (int j = 0; j < 10; j++) { sc[j] = expf(sc[j] - m); sum += sc[j]; }
#pragma unroll
        for (int o = 16; o; o >>= 1) sum += __shfl_xor_sync(0xffffffffu, sum, o);
        float inv = 1.f / sum;
#pragma unroll
        for (int j = 0; j < 10; j++) Pw[j*32 + lane] = sc[j] * inv;
        __syncwarp();

        float acc = 0.f;
#pragma unroll 4
        for (int k = 0; k < 300; k++)
            acc = fmaf(Pw[k], Vs[k*36 + lane], acc);

        int qg = half*150 + q;
        sa_in[((long)(qg*BSZ + b)) * DIM + h*DH + lane] = acc;
        __syncwarp();
    }
}

// ---------------- multi-scale deformable sampling (fp16 value) ----------------
__global__ void __launch_bounds__(256) deform_kernel(
    const float* __restrict__ offaw,
    const float* __restrict__ bbox, const __half* __restrict__ value,
    const int* __restrict__ spatial, const int* __restrict__ lstart,
    float* __restrict__ ca_in)
{
    __shared__ float s_w[8][32][4];
    __shared__ int   s_i[8][32][4];
    int bq = blockIdx.x;
    int b = bq / NQ, q = bq - b*NQ;
    int warp = threadIdx.x >> 5, lane = threadIdx.x & 31;

    const float* tok = offaw + (long)bq * 768;
    float a = tok[512 + warp*32 + lane];
    float m = a;
#pragma unroll
    for (int o = 16; o; o >>= 1) m = fmaxf(m, __shfl_xor_sync(0xffffffffu, m, o));
    float e = expf(a - m);
    float s = e;
#pragma unroll
    for (int o = 16; o; o >>= 1) s += __shfl_xor_sync(0xffffffffu, s, o);
    float p = e / s;

    float ox = tok[warp*64 + lane*2];
    float oy = tok[warp*64 + lane*2 + 1];
    const float* rb = bbox + ((long)q*BSZ + b)*4;
    float r0 = rb[0], r1 = rb[1], r2 = rb[2], r3 = rb[3];

    int lvl = lane >> 3;
    int H = spatial[lvl*2], W = spatial[lvl*2 + 1], ls = lstart[lvl];
    float Wf = (float)W, Hf = (float)H;
    float x = (r0 + ox*0.0625f*r2) * Wf - 0.5f;
    float y = (r1 + oy*0.0625f*r3) * Hf - 0.5f;
    float x0 = floorf(x), y0 = floorf(y);
    float fx = x - x0, fy = y - y0;

#pragma unroll
    for (int c = 0; c < 4; c++) {
        float xi = x0 + (float)(c & 1);
        float yi = y0 + (float)(c >> 1);
        float wgt = ((c & 1) ? fx : 1.f - fx) * ((c >> 1) ? fy : 1.f - fy);
        bool valid = (xi >= 0.f) && (xi < Wf) && (yi >= 0.f) && (yi < Hf);
        int xc = (int)fminf(fmaxf(xi, 0.f), Wf - 1.f);
        int yc = (int)fminf(fmaxf(yi, 0.f), Hf - 1.f);
        s_i[warp][lane][c] = ls + yc*W + xc;
        s_w[warp][lane][c] = valid ? wgt * p : 0.f;
    }
    __syncwarp();

    const __half* vb = value + (long)b * STOT * DIM + warp*DH + lane;
    float acc = 0.f;
    for (int lp = 0; lp < 32; lp++) {
#pragma unroll
        for (int c = 0; c < 4; c++) {
            float wgt = s_w[warp][lp][c];
            if (wgt != 0.f)
                acc = fmaf(wgt, __half2float(vb[(long)s_i[warp][lp][c] << 8]), acc);
        }
    }
    ca_in[(long)bq*DIM + warp*DH + lane] = acc;
}

// ---------------- host orchestration (single stream; no allocations) ----------------
extern "C" void kernel_launch(void* const* d_in, const int* in_sizes, int n_in,
                              void* d_out, int out_size)
{
    const float* tgt        = (const float*)d_in[0];
    const float* qmask      = (const float*)d_in[1];
    const float* bbox       = (const float*)d_in[2];
    const float* memory     = (const float*)d_in[4];
    const float* in_proj_w  = (const float*)d_in[5];
    const float* in_proj_b  = (const float*)d_in[6];
    const float* out_sa_w   = (const float*)d_in[7];
    const float* out_sa_b   = (const float*)d_in[8];
    const float* norm2_g    = (const float*)d_in[9];
    const float* norm2_b    = (const float*)d_in[10];
    const float* value_w    = (const float*)d_in[11];
    const float* value_b    = (const float*)d_in[12];
    const float* off_w      = (const float*)d_in[13];
    const float* off_b      = (const float*)d_in[14];
    const float* aw_w       = (const float*)d_in[15];
    const float* aw_b       = (const float*)d_in[16];
    const float* out_ca_w   = (const float*)d_in[17];
    const float* out_ca_b   = (const float*)d_in[18];
    const float* norm1_g    = (const float*)d_in[19];
    const float* norm1_b    = (const float*)d_in[20];
    const float* lin1_w     = (const float*)d_in[21];
    const float* lin1_b     = (const float*)d_in[22];
    const float* lin2_w     = (const float*)d_in[23];
    const float* lin2_b     = (const float*)d_in[24];
    const float* norm3_g    = (const float*)d_in[25];
    const float* norm3_b    = (const float*)d_in[26];
    const unsigned char* pmask = (const unsigned char*)d_in[27];
    const int* spatial      = (const int*)d_in[28];
    const int* lstart       = (const int*)d_in[29];
    float* out = (float*)d_out;

    float *qh,*kh,*vh,*sain,*saout,*tgt2,*offb,*cain,*caout,*tgt3,*f1,*f2;
    __half *wh,*val;
    cudaGetSymbolAddress((void**)&qh,    g_qh);
    cudaGetSymbolAddress((void**)&kh,    g_kh);
    cudaGetSymbolAddress((void**)&vh,    g_vh);
    cudaGetSymbolAddress((void**)&sain,  g_sain);
    cudaGetSymbolAddress((void**)&saout, g_saout);
    cudaGetSymbolAddress((void**)&tgt2,  g_tgt2);
    cudaGetSymbolAddress((void**)&offb,  g_off);
    cudaGetSymbolAddress((void**)&val,   g_value);
    cudaGetSymbolAddress((void**)&cain,  g_cain);
    cudaGetSymbolAddress((void**)&caout, g_caout);
    cudaGetSymbolAddress((void**)&tgt3,  g_tgt3);
    cudaGetSymbolAddress((void**)&f1,    g_f1);
    cudaGetSymbolAddress((void**)&f2,    g_f2);
    cudaGetSymbolAddress((void**)&wh,    g_wh);

    // 0) weight plane (fp16)
    {
        WDesc d;
        d.src[0]=in_proj_w; d.off[0]=W_INPROJ; d.n4[0]=196608/4;
        d.src[1]=out_sa_w;  d.off[1]=W_OUTSA;  d.n4[1]=65536/4;
        d.src[2]=value_w;   d.off[2]=W_VALUE;  d.n4[2]=65536/4;
        d.src[3]=off_w;     d.off[3]=W_OFF;    d.n4[3]=131072/4;
        d.src[4]=aw_w;      d.off[4]=W_AW;     d.n4[4]=65536/4;
        d.src[5]=out_ca_w;  d.off[5]=W_OUTCA;  d.n4[5]=65536/4;
        d.src[6]=lin1_w;    d.off[6]=W_LIN1;   d.n4[6]=262144/4;
        d.src[7]=lin2_w;    d.off[7]=W_LIN2;   d.n4[7]=262144/4;
        dim3 g((262144/4 + 255)/256, 8);
        cvt_w_kernel<<<g, 256>>>(d, wh);
    }

    // 1) value projection over memory (batched over BS), pad-mask fp16 epilogue
    launch_mma(3, memory, nullptr, 0, 0, BSZ*DIM, 256, wh+W_VALUE, DIM, value_b,
               nullptr, nullptr, 0,
               (float*)val, nullptr, nullptr, DIM, (long)STOT*DIM,
               STOT, DIM, DIM, BSZ, pmask, STOT);

    // 2) merged QKV projection (N=768): Q,K read tgt+qmask (bn<512), V reads tgt
    launch_mma(2, tgt, qmask, 2, 0, DIM, 0, wh+W_INPROJ, DIM, in_proj_b,
               nullptr, nullptr, 0,
               qh, kh, vh, 0, 0, NTOK, 768, DIM, 1, nullptr, 0);

    // 3) fused self-attention
    {
        int smem = (300*36*2 + 150*32 + 8*320) * 4;
        cudaFuncSetAttribute(attn_kernel, cudaFuncAttributeMaxDynamicSharedMemorySize, smem);
        attn_kernel<<<128, 256, smem>>>(qh, kh, vh, sain);
    }

    // 4) self-attn out-proj + residual LN (norm2)
    launch_mma(0, sain, nullptr, 0, 0, DIM, 0, wh+W_OUTSA, DIM, out_sa_b,
               nullptr, nullptr, 0,
               saout, nullptr, nullptr, DIM, 0, NTOK, DIM, DIM, 1, nullptr, 0);
    ln_kernel<<<NTOK/8, 256>>>(tgt, saout, 0, norm2_g, norm2_b, tgt2);

    // 5) offsets + aw logits merged (N=768, W split at 512); A = perm(tgt2 + qmask)
    launch_mma(0, tgt2, qmask, 1, 1, DIM, 0, wh+W_OFF, DIM, off_b,
               wh+W_AW, aw_b, 512,
               offb, nullptr, nullptr, 768, 0, NTOK, 768, DIM, 1, nullptr, 0);

    // 6) deformable sampling (fp16 value)
    deform_kernel<<<NTOK, 256>>>(offb, bbox, val, spatial, lstart, cain);

    // 7) cross-attn out-proj + residual LN (norm1)
    launch_mma(0, cain, nullptr, 0, 0, DIM, 0, wh+W_OUTCA, DIM, out_ca_b,
               nullptr, nullptr, 0,
               caout, nullptr, nullptr, DIM, 0, NTOK, DIM, DIM, 1, nullptr, 0);
    ln_kernel<<<NTOK/8, 256>>>(tgt2, caout, 1, norm1_g, norm1_b, tgt3);

    // 8) FFN + final LN (norm3) -> d_out
    launch_mma(1, tgt3, nullptr, 0, 0, DIM, 0, wh+W_LIN1, DIM, lin1_b,
               nullptr, nullptr, 0,
               f1, nullptr, nullptr, DFF, 0, NTOK, DFF, DIM, 1, nullptr, 0);
    launch_mma(0, f1, nullptr, 0, 0, DFF, 0, wh+W_LIN2, DFF, lin2_b,
               nullptr, nullptr, 0,
               f2, nullptr, nullptr, DIM, 0, NTOK, DIM, DFF, 1, nullptr, 0);
    ln_kernel<<<NTOK/8, 256>>>(tgt3, f2, 0, norm3_g, norm3_b, out);
}